// round 4
// baseline (speedup 1.0000x reference)
#include <cuda_runtime.h>

#define H_IN 512
#define W_IN 512
#define HW (H_IN * W_IN)
#define BC 96            // 32 batch * 3 channels
#define BC_PER_THREAD 4
#define BC_CHUNKS (BC / BC_PER_THREAD)   // 24

// max_r = log(norm(512,512)/2 * 2.0) = log(512*sqrt(2))
#define MAX_R 6.58489821531948f
#define PI_F 3.14159265358979323846f

// Precomputed per-pixel map (scratch; __device__ globals are allowed).
// meta bits: [0:18) o0 (aligned float2 offset, row y_down)
//            bit18 odd(x_down)   bit19 row_same(y_up==y_down)
//            bit20 de1 (extra-tap delta==1, i.e. x_down==511)
//            bit21 mask
__device__ unsigned int g_meta[HW];
__device__ float4       g_wts[HW];

__global__ __launch_bounds__(256) void map_kernel()
{
    const int pix = blockIdx.x * blockDim.x + threadIdx.x;
    const int h = pix >> 9;
    const int w = pix & 511;

    // Match reference fp32 rounding.
    const float ang = (float)(2 * h) * PI_F * (1.0f / 512.0f);
    const float radius = expf((float)w * MAX_R * (1.0f / 512.0f));
    float s, c;
    sincosf(ang, &s, &c);
    const float X = 256.0f + radius * c;
    const float Y = 256.0f - radius * s;

    const bool mask = (X >= 0.0f) && (X < 512.0f) && (Y >= 0.0f) && (Y < 512.0f);

    unsigned int meta = 0u;
    float4 wv = make_float4(0.f, 0.f, 0.f, 0.f);
    if (mask) {
        int y_down = (int)Y; y_down = min(max(y_down, 0), H_IN - 1);
        int x_down = (int)X; x_down = min(max(x_down, 0), W_IN - 1);
        const int y_up = min(y_down + 1, H_IN - 1);
        const int x_up = min(x_down + 1, W_IN - 1);

        const float yd = Y - (float)y_down;
        const float yu = Y - (float)y_up;
        const float xd = X - (float)x_down;
        const float xu = X - (float)x_up;

        const float dd = yd * yd + xd * xd;
        const float du = yd * yd + xu * xu;
        const float ud = yu * yu + xd * xd;
        const float uu = yu * yu + xu * xu;
        const float inv_total = 1.0f / (dd + du + ud + uu);

        wv = make_float4(dd * inv_total, du * inv_total,
                         ud * inv_total, uu * inv_total);

        const int xb = x_down & ~1;
        const unsigned int odd = (unsigned)(x_down & 1);
        const unsigned int row_same = (y_down == H_IN - 1) ? 1u : 0u;
        const unsigned int de1 = (x_down == W_IN - 1) ? 1u : 0u;
        meta = (unsigned)(y_down * W_IN + xb)
             | (odd << 18) | (row_same << 19) | (de1 << 20) | (1u << 21);
    }
    g_meta[pix] = meta;
    g_wts[pix]  = wv;
}

__global__ __launch_bounds__(256) void gather_kernel(
    const float* __restrict__ in, float* __restrict__ out)
{
    const int pix = blockIdx.x * blockDim.x + threadIdx.x;
    const int bc0 = blockIdx.y * BC_PER_THREAD;

    const unsigned int meta = __ldg(&g_meta[pix]);
    float* q = out + (size_t)bc0 * HW + pix;

    if (meta >> 21) {
        const float4 wv = __ldg(&g_wts[pix]);
        const int  o0  = (int)(meta & 0x3FFFFu);
        const int  o1  = o0 + (((meta >> 19) & 1u) ? 0 : W_IN);
        const bool odd = ((meta >> 18) & 1u) != 0u;
        const int  de  = ((meta >> 20) & 1u) ? 1 : 2;

        const float* p = in + (size_t)bc0 * HW;

        float2 a[BC_PER_THREAD], b[BC_PER_THREAD];
        float  e0[BC_PER_THREAD], e1[BC_PER_THREAD];
        #pragma unroll
        for (int i = 0; i < BC_PER_THREAD; ++i) {
            const float* pi_ = p + (size_t)i * HW;
            a[i] = __ldg((const float2*)(pi_ + o0));
            b[i] = __ldg((const float2*)(pi_ + o1));
            if (odd) {
                e0[i] = __ldg(pi_ + o0 + de);
                e1[i] = __ldg(pi_ + o1 + de);
            }
        }
        #pragma unroll
        for (int i = 0; i < BC_PER_THREAD; ++i) {
            const float v00 = odd ? a[i].y : a[i].x;
            const float v01 = odd ? e0[i]  : a[i].y;
            const float v10 = odd ? b[i].y : b[i].x;
            const float v11 = odd ? e1[i]  : b[i].y;
            q[(size_t)i * HW] = wv.x * v00 + wv.y * v01
                              + wv.z * v10 + wv.w * v11;
        }
    } else {
        #pragma unroll
        for (int i = 0; i < BC_PER_THREAD; ++i) {
            q[(size_t)i * HW] = 0.0f;
        }
    }
}

extern "C" void kernel_launch(void* const* d_in, const int* in_sizes, int n_in,
                              void* d_out, int out_size)
{
    const float* data = (const float*)d_in[0];
    float* out = (float*)d_out;
    map_kernel<<<HW / 256, 256>>>();
    dim3 grid(HW / 256, BC_CHUNKS);   // (1024, 24)
    gather_kernel<<<grid, 256>>>(data, out);
}